// round 1
// baseline (speedup 1.0000x reference)
#include <cuda_runtime.h>
#include <math.h>
#include <stdint.h>

// Problem constants
#define Hdim 512
#define Lsteps 16
#define Nrows 8192
#define NH (Nrows * Hdim)        // 4,194,304

// ---------------- scratch (device globals; no allocation allowed) -------------
__device__ float g_P[Lsteps * (size_t)NH];   // precomputed el@W2 + xl@W4 (256 MB)
__device__ float g_C0[NH];                   // x0@W3 + b_xi
__device__ float g_X0H[NH];                  // (1-xi)*x0
__device__ float g_XTH[NH];                  // xi*xl
__device__ float g_RH[NH];                   // r*hx
__device__ float g_U[NH];                    // u gate

// ---------------- GEMM config -------------------------------------------------
#define BM 128
#define BN 128
#define BK 32
#define APAD 4
#define BPAD 4
#define AS_STRIDE (BK + APAD)            // 36
#define BS_STRIDE (BN + BPAD)            // 132
#define AS_BUF (BM * AS_STRIDE)          // 4608 floats
#define BS_BUF (BK * BS_STRIDE)          // 4224 floats
#define SMEM_FLOATS (2 * AS_BUF + 2 * BS_BUF)
#define SMEM_BYTES (SMEM_FLOATS * 4)     // 70656

struct GemmArgs {
    const float* A[3];          // A sources, one per 512-wide K block (row-major, ld=512)
    const float* B[3][2];       // B sources [kblock][jblock], each ld=512, row-major
    int ksplits;                // K = 512 * ksplits
    // epilogue operands
    const float* P;             // (pre-offset by step)
    const float* C0;
    const float* x0;
    const float* xl;
    const float* bias0;
    const float* bias1;
    const float* hx;
    const float* U;
    float* out0;
    float* out1;
};

__device__ __forceinline__ float tf32_rna(float x) {
    uint32_t u;
    asm("cvt.rna.tf32.f32 %0, %1;" : "=r"(u) : "f"(x));
    return __uint_as_float(u);
}

__device__ __forceinline__ float4 tf32_rna4(float4 v) {
    v.x = tf32_rna(v.x); v.y = tf32_rna(v.y);
    v.z = tf32_rna(v.z); v.w = tf32_rna(v.w);
    return v;
}

__device__ __forceinline__ float sigmoidf_(float x) {
    return 1.0f / (1.0f + expf(-x));
}

// MODES
#define MODE_PRE 0
#define MODE_C0  1
#define MODE_XI  2
#define MODE_UR  3
#define MODE_K   4

template <int MODE>
__device__ __forceinline__ void epi(const GemmArgs& g, int row, int col, float v0, float v1) {
    size_t base = (size_t)row * Hdim;
    if (MODE == MODE_PRE) {
        *(float2*)(g.out0 + base + col) = make_float2(v0, v1);
    } else if (MODE == MODE_C0) {
        *(float2*)(g.out0 + base + col) =
            make_float2(v0 + g.bias0[col], v1 + g.bias0[col + 1]);
    } else if (MODE == MODE_XI) {
        size_t idx = base + col;
        float2 p   = *(const float2*)(g.P  + idx);
        float2 c0v = *(const float2*)(g.C0 + idx);
        float2 x0v = *(const float2*)(g.x0 + idx);
        float2 xlv = *(const float2*)(g.xl + idx);
        float s0 = sigmoidf_(v0 + p.x + c0v.x);
        float s1 = sigmoidf_(v1 + p.y + c0v.y);
        *(float2*)(g.out0 + idx) = make_float2((1.0f - s0) * x0v.x, (1.0f - s1) * x0v.y);
        *(float2*)(g.out1 + idx) = make_float2(s0 * xlv.x, s1 * xlv.y);
    } else if (MODE == MODE_UR) {
        if (col < Hdim) {
            size_t idx = base + col;
            *(float2*)(g.out0 + idx) =
                make_float2(sigmoidf_(v0 + g.bias0[col]), sigmoidf_(v1 + g.bias0[col + 1]));
        } else {
            int cc = col - Hdim;
            size_t idx = base + cc;
            float2 h = *(const float2*)(g.hx + idx);
            *(float2*)(g.out1 + idx) =
                make_float2(sigmoidf_(v0 + g.bias1[cc]) * h.x,
                            sigmoidf_(v1 + g.bias1[cc + 1]) * h.y);
        }
    } else { // MODE_K
        size_t idx = base + col;
        float2 u = *(const float2*)(g.U + idx);
        float2 h = *(const float2*)(g.hx + idx);
        float k0 = tanhf(v0 + g.bias0[col]);
        float k1 = tanhf(v1 + g.bias0[col + 1]);
        *(float2*)(g.out0 + idx) =
            make_float2((1.0f - u.x) * k0 + u.x * h.x, (1.0f - u.y) * k1 + u.y * h.y);
    }
}

__device__ __forceinline__ void load_g(const GemmArgs& args, int kb, int tid,
                                       int rowBase, int cb, int jsrc,
                                       float4 (&av)[4], float4 (&bv)[4]) {
    const float* Asrc = args.A[kb >> 4];
    const float* Bsrc = args.B[kb >> 4][jsrc];
    int kloc = (kb & 15) << 5;       // k offset within 512 block
    int r = tid >> 3;                // 0..31
    int q = (tid & 7) << 2;          // 0,4,..,28
    const float* ap = Asrc + (size_t)(rowBase + r) * Hdim + kloc + q;
#pragma unroll
    for (int p = 0; p < 4; ++p)
        av[p] = *(const float4*)(ap + (size_t)(32 * p) * Hdim);
    const float* bp = Bsrc + (size_t)(kloc + r) * Hdim + cb + q;
#pragma unroll
    for (int p = 0; p < 4; ++p)
        bv[p] = *(const float4*)(bp + 32 * p);
}

__device__ __forceinline__ void store_s(float* As, float* Bs, int buf, int tid,
                                        const float4 (&av)[4], const float4 (&bv)[4]) {
    int r = tid >> 3;
    int q = (tid & 7) << 2;
    float* ab = As + buf * AS_BUF;
    float* bb = Bs + buf * BS_BUF;
#pragma unroll
    for (int p = 0; p < 4; ++p)
        *(float4*)&ab[(r + 32 * p) * AS_STRIDE + q] = tf32_rna4(av[p]);
#pragma unroll
    for (int p = 0; p < 4; ++p)
        *(float4*)&bb[r * BS_STRIDE + q + 32 * p] = tf32_rna4(bv[p]);
}

__device__ __forceinline__ void mma_tile(float (&d)[4], const uint32_t (&a)[4],
                                         const uint32_t (&b)[2]) {
    asm volatile(
        "mma.sync.aligned.m16n8k8.row.col.f32.tf32.tf32.f32 "
        "{%0,%1,%2,%3}, {%4,%5,%6,%7}, {%8,%9}, {%0,%1,%2,%3};"
        : "+f"(d[0]), "+f"(d[1]), "+f"(d[2]), "+f"(d[3])
        : "r"(a[0]), "r"(a[1]), "r"(a[2]), "r"(a[3]), "r"(b[0]), "r"(b[1]));
}

__device__ __forceinline__ void compute_tile(const float* As, const float* Bs, int buf,
                                             int wm, int wn, int g, int c,
                                             float (&acc)[2][8][4]) {
    const float* Ab = As + buf * AS_BUF;
    const float* Bb = Bs + buf * BS_BUF;
#pragma unroll
    for (int s = 0; s < 4; ++s) {
        int kk = s << 3;
        uint32_t af[2][4];
        uint32_t bf[8][2];
#pragma unroll
        for (int i = 0; i < 2; ++i) {
            const float* a0 = Ab + (wm * 32 + i * 16 + g) * AS_STRIDE + kk + c;
            af[i][0] = __float_as_uint(a0[0]);
            af[i][1] = __float_as_uint(a0[8 * AS_STRIDE]);
            af[i][2] = __float_as_uint(a0[4]);
            af[i][3] = __float_as_uint(a0[8 * AS_STRIDE + 4]);
        }
#pragma unroll
        for (int t = 0; t < 8; ++t) {
            const float* b0 = Bb + (kk + c) * BS_STRIDE + wn * 64 + t * 8 + g;
            bf[t][0] = __float_as_uint(b0[0]);
            bf[t][1] = __float_as_uint(b0[4 * BS_STRIDE]);
        }
#pragma unroll
        for (int i = 0; i < 2; ++i)
#pragma unroll
            for (int t = 0; t < 8; ++t)
                mma_tile(acc[i][t], af[i], bf[t]);
    }
}

template <int MODE>
__global__ void __launch_bounds__(256, 2) gemm_tf32(GemmArgs args) {
    extern __shared__ float smem[];
    float* As = smem;
    float* Bs = smem + 2 * AS_BUF;

    int tid = threadIdx.x;
    int warp = tid >> 5;
    int lane = tid & 31;
    int wm = warp & 3;        // 4 warps along M
    int wn = warp >> 2;       // 2 warps along N
    int g = lane >> 2;
    int c = lane & 3;

    int rowBase = blockIdx.x * BM;
    int colBase = blockIdx.y * BN;
    int jsrc = colBase >> 9;          // which 512-wide output half
    int cb = colBase & 511;
    int kblocks = args.ksplits << 4;  // K / 32

    float acc[2][8][4];
#pragma unroll
    for (int i = 0; i < 2; ++i)
#pragma unroll
        for (int t = 0; t < 8; ++t)
#pragma unroll
            for (int e = 0; e < 4; ++e) acc[i][t][e] = 0.0f;

    float4 av[4], bv[4];
    load_g(args, 0, tid, rowBase, cb, jsrc, av, bv);
    store_s(As, Bs, 0, tid, av, bv);
    __syncthreads();

    for (int kb = 0; kb < kblocks; ++kb) {
        int cur = kb & 1;
        bool more = (kb + 1) < kblocks;
        if (more) load_g(args, kb + 1, tid, rowBase, cb, jsrc, av, bv);
        compute_tile(As, Bs, cur, wm, wn, g, c, acc);
        if (more) store_s(As, Bs, cur ^ 1, tid, av, bv);
        __syncthreads();
    }

    // epilogue
#pragma unroll
    for (int i = 0; i < 2; ++i) {
#pragma unroll
        for (int t = 0; t < 8; ++t) {
            int rl = rowBase + wm * 32 + i * 16 + g;
            int cl = colBase + wn * 64 + t * 8 + 2 * c;
            epi<MODE>(args, rl, cl, acc[i][t][0], acc[i][t][1]);
            epi<MODE>(args, rl + 8, cl, acc[i][t][2], acc[i][t][3]);
        }
    }
}

template <int MODE>
static void run_gemm(const GemmArgs& a, int M, int nTiles) {
    cudaFuncSetAttribute(gemm_tf32<MODE>, cudaFuncAttributeMaxDynamicSharedMemorySize,
                         SMEM_BYTES);
    dim3 grid(M / BM, nTiles);
    gemm_tf32<MODE><<<grid, 256, SMEM_BYTES>>>(a);
}

extern "C" void kernel_launch(void* const* d_in, const int* in_sizes, int n_in,
                              void* d_out, int out_size) {
    const float* edge = (const float*)d_in[0];   // (L, N, H)
    const float* node = (const float*)d_in[1];   // (L+1, N, H)
    const float* W_xi = (const float*)d_in[2];   // (4H, H)
    const float* b_xi = (const float*)d_in[3];
    const float* W_u  = (const float*)d_in[4];   // (3H, H)
    const float* b_u  = (const float*)d_in[5];
    const float* W_r  = (const float*)d_in[6];
    const float* b_r  = (const float*)d_in[7];
    const float* W_k  = (const float*)d_in[8];
    const float* b_k  = (const float*)d_in[9];
    float* hx = (float*)d_out;                   // used as the recurrent state

    float *P, *C0, *X0H, *XTH, *RH, *U;
    cudaGetSymbolAddress((void**)&P,   g_P);
    cudaGetSymbolAddress((void**)&C0,  g_C0);
    cudaGetSymbolAddress((void**)&X0H, g_X0H);
    cudaGetSymbolAddress((void**)&XTH, g_XTH);
    cudaGetSymbolAddress((void**)&RH,  g_RH);
    cudaGetSymbolAddress((void**)&U,   g_U);

    const float* x0 = node + (size_t)Lsteps * NH;

    // hx0 = 0
    cudaMemsetAsync(d_out, 0, (size_t)out_size * sizeof(float), 0);

    // ---- Precompute P[l] = el @ W_xi[H:2H] + xl @ W_xi[3H:4H]  (M = L*N, K = 1024)
    {
        GemmArgs a = {};
        a.A[0] = edge;
        a.A[1] = node;                       // rows 0..L*N-1 are xl
        a.B[0][0] = W_xi + (size_t)1 * Hdim * Hdim;   // W2 rows [H, 2H)
        a.B[1][0] = W_xi + (size_t)3 * Hdim * Hdim;   // W4 rows [3H, 4H)
        a.ksplits = 2;
        a.out0 = P;
        run_gemm<MODE_PRE>(a, Lsteps * Nrows, Hdim / BN);
    }

    // ---- C0 = x0 @ W_xi[2H:3H] + b_xi   (M = N, K = 512)
    {
        GemmArgs a = {};
        a.A[0] = x0;
        a.B[0][0] = W_xi + (size_t)2 * Hdim * Hdim;   // W3 rows [2H, 3H)
        a.ksplits = 1;
        a.bias0 = b_xi;
        a.out0 = C0;
        run_gemm<MODE_C0>(a, Nrows, Hdim / BN);
    }

    // ---- Sequential recurrence
    for (int l = 0; l < Lsteps; ++l) {
        // xi gate -> X0H, XTH
        {
            GemmArgs a = {};
            a.A[0] = hx;
            a.B[0][0] = W_xi;                 // rows [0, H)
            a.ksplits = 1;
            a.P  = P + (size_t)l * NH;
            a.C0 = C0;
            a.x0 = x0;
            a.xl = node + (size_t)l * NH;
            a.out0 = X0H;
            a.out1 = XTH;
            run_gemm<MODE_XI>(a, Nrows, Hdim / BN);
        }
        // fused u | r gates -> U, RH = r*hx
        {
            GemmArgs a = {};
            a.A[0] = hx;
            a.A[1] = X0H;
            a.A[2] = XTH;
            for (int kbl = 0; kbl < 3; ++kbl) {
                a.B[kbl][0] = W_u + (size_t)kbl * Hdim * Hdim;
                a.B[kbl][1] = W_r + (size_t)kbl * Hdim * Hdim;
            }
            a.ksplits = 3;
            a.bias0 = b_u;
            a.bias1 = b_r;
            a.hx = hx;
            a.out0 = U;
            a.out1 = RH;
            run_gemm<MODE_UR>(a, Nrows, 2 * Hdim / BN);
        }
        // k gate + state update -> hx (in place)
        {
            GemmArgs a = {};
            a.A[0] = X0H;
            a.A[1] = XTH;
            a.A[2] = RH;
            for (int kbl = 0; kbl < 3; ++kbl)
                a.B[kbl][0] = W_k + (size_t)kbl * Hdim * Hdim;
            a.ksplits = 3;
            a.bias0 = b_k;
            a.U = U;
            a.hx = hx;
            a.out0 = hx;
            run_gemm<MODE_K>(a, Nrows, Hdim / BN);
        }
    }
}

// round 3
// speedup vs baseline: 1.0587x; 1.0587x over previous
#include <cuda_runtime.h>
#include <math.h>
#include <stdint.h>

// Problem constants
#define Hdim 512
#define Lsteps 16
#define Nrows 8192
#define NH (Nrows * Hdim)

// ---------------- scratch (device globals) ------------------------------------
__device__ float g_P[Lsteps * (size_t)NH];   // precomputed el@W2 + xl@W4
__device__ float g_C0[NH];                   // x0@W3 + b_xi
__device__ float g_X0H[NH];                  // (1-xi)*x0   (rna-rounded)
__device__ float g_XTH[NH];                  // xi*xl       (rna-rounded)
__device__ float g_RH[NH];                   // r*hx        (rna-rounded)
__device__ float g_U[NH];                    // u gate
// transposed (and tf32-rna-rounded) weights [n][k]
__device__ float g_W1T[512 * 512];
__device__ float g_WpT[512 * 1024];
__device__ float g_W3T[512 * 512];
__device__ float g_WurT[1024 * 1536];
__device__ float g_WkT[512 * 1536];

// ---------------- helpers -------------------------------------------------------
__device__ __forceinline__ uint32_t smem_u32(const void* p) {
    uint32_t a;
    asm("{ .reg .u64 t; cvta.to.shared.u64 t, %1; cvt.u32.u64 %0, t; }" : "=r"(a) : "l"(p));
    return a;
}
__device__ __forceinline__ void cp_async16(float* dst, const float* src) {
    asm volatile("cp.async.cg.shared.global [%0], [%1], 16;"
                 :: "r"(smem_u32(dst)), "l"(src) : "memory");
}
#define CP_COMMIT() asm volatile("cp.async.commit_group;" ::: "memory")
#define CP_WAIT1()  asm volatile("cp.async.wait_group 1;" ::: "memory")

__device__ __forceinline__ float tf32_rna(float x) {
    uint32_t u;
    asm("cvt.rna.tf32.f32 %0, %1;" : "=r"(u) : "f"(x));
    return __uint_as_float(u);
}
__device__ __forceinline__ float sigmoidf_(float x) { return 1.0f / (1.0f + expf(-x)); }

// ---------------- GEMM config ---------------------------------------------------
// CTA 128x128x32, 4 warps (warp tile 64x64), 3-stage cp.async pipeline.
#define BK 32
#define ROW_F 36                       // 32 + 4 pad floats per smem row
#define STAGE_A_F (128 * ROW_F)        // 4608 floats
#define STAGE_F (2 * STAGE_A_F)        // A then B, 9216 floats = 36864 B
#define NSTAGE 3
#define SMEM_BYTES (NSTAGE * STAGE_F * 4)  // 110592

struct GemmArgs {
    const float* A[3];          // K blocks of 512 (row-major, ld = 512)
    const float* Bt;            // transposed weights [Ntot][Ktot]
    int ldB;
    const float* P;
    const float* C0;
    const float* x0;
    const float* xl;
    const float* bias0;
    const float* bias1;
    const float* hx;
    const float* U;
    float* out0;
    float* out1;
};

#define MODE_PRE 0
#define MODE_C0  1
#define MODE_XI  2
#define MODE_UR  3
#define MODE_K   4

template <int MODE>
__device__ __forceinline__ void epi(const GemmArgs& g, int row, int col, float v0, float v1) {
    int c512 = col & 511;
    size_t idx = (size_t)row * Hdim + c512;
    if (MODE == MODE_PRE) {
        *(float2*)(g.out0 + idx) = make_float2(v0, v1);
    } else if (MODE == MODE_C0) {
        float2 b = *(const float2*)(g.bias0 + c512);
        *(float2*)(g.out0 + idx) = make_float2(v0 + b.x, v1 + b.y);
    } else if (MODE == MODE_XI) {
        float2 p   = *(const float2*)(g.P  + idx);
        float2 c0v = *(const float2*)(g.C0 + idx);
        float2 x0v = *(const float2*)(g.x0 + idx);
        float2 xlv = *(const float2*)(g.xl + idx);
        float s0 = sigmoidf_(v0 + p.x + c0v.x);
        float s1 = sigmoidf_(v1 + p.y + c0v.y);
        *(float2*)(g.out0 + idx) = make_float2(tf32_rna((1.f - s0) * x0v.x),
                                               tf32_rna((1.f - s1) * x0v.y));
        *(float2*)(g.out1 + idx) = make_float2(tf32_rna(s0 * xlv.x), tf32_rna(s1 * xlv.y));
    } else if (MODE == MODE_UR) {
        if (col < Hdim) {
            float2 b = *(const float2*)(g.bias0 + c512);
            *(float2*)(g.out0 + idx) = make_float2(sigmoidf_(v0 + b.x), sigmoidf_(v1 + b.y));
        } else {
            float2 b = *(const float2*)(g.bias1 + c512);
            float2 h = *(const float2*)(g.hx + idx);
            *(float2*)(g.out1 + idx) = make_float2(tf32_rna(sigmoidf_(v0 + b.x) * h.x),
                                                   tf32_rna(sigmoidf_(v1 + b.y) * h.y));
        }
    } else { // MODE_K
        float2 b = *(const float2*)(g.bias0 + c512);
        float2 u = *(const float2*)(g.U + idx);
        float2 h = *(const float2*)(g.hx + idx);
        float k0 = tanhf(v0 + b.x), k1 = tanhf(v1 + b.y);
        *(float2*)(g.out0 + idx) = make_float2(tf32_rna((1.f - u.x) * k0 + u.x * h.x),
                                               tf32_rna((1.f - u.y) * k1 + u.y * h.y));
    }
}

__device__ __forceinline__ void issue_stage(const GemmArgs& g, int kb, int tid,
                                            int rowBase, int colBase, float* sm) {
    float* As = sm;
    float* Bs = sm + STAGE_A_F;
    int c = tid & 7;                 // 16B chunk within row
    int r = tid >> 3;                // 0..15
    const float* asrc = g.A[kb >> 4] + (size_t)(rowBase + r) * Hdim + (kb & 15) * 32 + c * 4;
    const float* bsrc = g.Bt + (size_t)(colBase + r) * g.ldB + kb * 32 + c * 4;
#pragma unroll
    for (int rr = 0; rr < 8; ++rr) {
        cp_async16(&As[(r + 16 * rr) * ROW_F + c * 4], asrc + (size_t)(16 * rr) * Hdim);
        cp_async16(&Bs[(r + 16 * rr) * ROW_F + c * 4], bsrc + (size_t)(16 * rr) * g.ldB);
    }
}

__device__ __forceinline__ void mma_tf32(float (&d)[4], const uint32_t (&a)[4],
                                         const uint32_t (&b)[2]) {
    asm volatile(
        "mma.sync.aligned.m16n8k8.row.col.f32.tf32.tf32.f32 "
        "{%0,%1,%2,%3}, {%4,%5,%6,%7}, {%8,%9}, {%0,%1,%2,%3};"
        : "+f"(d[0]), "+f"(d[1]), "+f"(d[2]), "+f"(d[3])
        : "r"(a[0]), "r"(a[1]), "r"(a[2]), "r"(a[3]), "r"(b[0]), "r"(b[1]));
}

__device__ __forceinline__ void compute_stage(const float* sm, int MW, int NW,
                                              int g, int c, float (&acc)[4][8][4]) {
    const float* As = sm;
    const float* Bs = sm + STAGE_A_F;
#pragma unroll
    for (int kk = 0; kk < BK; kk += 8) {
        uint32_t af[4][4];
        uint32_t bf[8][2];
#pragma unroll
        for (int i = 0; i < 4; ++i) {
            const float* a0 = As + (MW + i * 16 + g) * ROW_F + kk + c;
            af[i][0] = __float_as_uint(a0[0]);
            af[i][1] = __float_as_uint(a0[8 * ROW_F]);
            af[i][2] = __float_as_uint(a0[4]);
            af[i][3] = __float_as_uint(a0[8 * ROW_F + 4]);
        }
#pragma unroll
        for (int j = 0; j < 8; ++j) {
            const float* b0 = Bs + (NW + j * 8 + g) * ROW_F + kk + c;
            bf[j][0] = __float_as_uint(b0[0]);
            bf[j][1] = __float_as_uint(b0[4]);
        }
#pragma unroll
        for (int i = 0; i < 4; ++i)
#pragma unroll
            for (int j = 0; j < 8; ++j)
                mma_tf32(acc[i][j], af[i], bf[j]);
    }
}

template <int MODE>
__global__ void __launch_bounds__(128, 2) gemm_cp(GemmArgs args, int kblocks) {
    extern __shared__ float sm[];
    int tid = threadIdx.x;
    int warp = tid >> 5, lane = tid & 31;
    int MW = (warp & 1) * 64, NW = (warp >> 1) * 64;
    int g = lane >> 2, c = lane & 3;
    int rowBase = blockIdx.x * 128, colBase = blockIdx.y * 128;

    float acc[4][8][4];
#pragma unroll
    for (int i = 0; i < 4; ++i)
#pragma unroll
        for (int j = 0; j < 8; ++j)
#pragma unroll
            for (int e = 0; e < 4; ++e) acc[i][j][e] = 0.0f;

    issue_stage(args, 0, tid, rowBase, colBase, sm);
    CP_COMMIT();
    if (kblocks > 1) issue_stage(args, 1, tid, rowBase, colBase, sm + STAGE_F);
    CP_COMMIT();

    int stage = 0;
    for (int kb = 0; kb < kblocks; ++kb) {
        CP_WAIT1();
        __syncthreads();
        if (kb + 2 < kblocks) {
            int ns = stage + 2;
            if (ns >= NSTAGE) ns -= NSTAGE;
            issue_stage(args, kb + 2, tid, rowBase, colBase, sm + ns * STAGE_F);
        }
        CP_COMMIT();
        compute_stage(sm + stage * STAGE_F, MW, NW, g, c, acc);
        if (++stage == NSTAGE) stage = 0;
    }

    // epilogue
#pragma unroll
    for (int i = 0; i < 4; ++i) {
#pragma unroll
        for (int j = 0; j < 8; ++j) {
            int row = rowBase + MW + i * 16 + g;
            int col = colBase + NW + j * 8 + 2 * c;
            epi<MODE>(args, row, col, acc[i][j][0], acc[i][j][1]);
            epi<MODE>(args, row + 8, col, acc[i][j][2], acc[i][j][3]);
        }
    }
}

// ---------------- weight transpose (+ tf32 rna rounding) ------------------------
__global__ void transposeW(const float* src, float* dst, int dstld) {
    __shared__ float t[32][33];
    int tx = threadIdx.x, ty = threadIdx.y;
    int kb = blockIdx.x * 32, nb = blockIdx.y * 32;
#pragma unroll
    for (int i = 0; i < 32; i += 8)
        t[ty + i][tx] = src[(size_t)(kb + ty + i) * 512 + nb + tx];
    __syncthreads();
#pragma unroll
    for (int i = 0; i < 32; i += 8)
        dst[(size_t)(nb + ty + i) * dstld + kb + tx] = tf32_rna(t[tx][ty + i]);
}

// ---------------- host -----------------------------------------------------------
template <int MODE>
static void run_gemm(const GemmArgs& a, int M, int nTiles, int kblocks) {
    cudaFuncSetAttribute(gemm_cp<MODE>, cudaFuncAttributeMaxDynamicSharedMemorySize,
                         SMEM_BYTES);
    dim3 grid(M / 128, nTiles);
    gemm_cp<MODE><<<grid, 128, SMEM_BYTES>>>(a, kblocks);
}

extern "C" void kernel_launch(void* const* d_in, const int* in_sizes, int n_in,
                              void* d_out, int out_size) {
    const float* edge = (const float*)d_in[0];
    const float* node = (const float*)d_in[1];
    const float* W_xi = (const float*)d_in[2];
    const float* b_xi = (const float*)d_in[3];
    const float* W_u  = (const float*)d_in[4];
    const float* b_u  = (const float*)d_in[5];
    const float* W_r  = (const float*)d_in[6];
    const float* b_r  = (const float*)d_in[7];
    const float* W_k  = (const float*)d_in[8];
    const float* b_k  = (const float*)d_in[9];
    float* hx = (float*)d_out;

    float *P, *C0, *X0H, *XTH, *RH, *U, *W1T, *WpT, *W3T, *WurT, *WkT;
    cudaGetSymbolAddress((void**)&P,    g_P);
    cudaGetSymbolAddress((void**)&C0,   g_C0);
    cudaGetSymbolAddress((void**)&X0H,  g_X0H);
    cudaGetSymbolAddress((void**)&XTH,  g_XTH);
    cudaGetSymbolAddress((void**)&RH,   g_RH);
    cudaGetSymbolAddress((void**)&U,    g_U);
    cudaGetSymbolAddress((void**)&W1T,  g_W1T);
    cudaGetSymbolAddress((void**)&WpT,  g_WpT);
    cudaGetSymbolAddress((void**)&W3T,  g_W3T);
    cudaGetSymbolAddress((void**)&WurT, g_WurT);
    cudaGetSymbolAddress((void**)&WkT,  g_WkT);

    const float* x0 = node + (size_t)Lsteps * NH;

    cudaMemsetAsync(d_out, 0, (size_t)out_size * sizeof(float), 0);

    // transpose weights into K-major [n][k] with tf32 rounding
    dim3 tb(32, 8);
    transposeW<<<dim3(16, 16), tb>>>(W_xi,              W1T, 512);
    transposeW<<<dim3(16, 16), tb>>>(W_xi + 512 * 512,  WpT, 1024);
    transposeW<<<dim3(16, 16), tb>>>(W_xi + 1536 * 512, WpT + 512, 1024);
    transposeW<<<dim3(16, 16), tb>>>(W_xi + 1024 * 512, W3T, 512);
    transposeW<<<dim3(48, 16), tb>>>(W_u,               WurT, 1536);
    transposeW<<<dim3(48, 16), tb>>>(W_r,               WurT + (size_t)512 * 1536, 1536);
    transposeW<<<dim3(48, 16), tb>>>(W_k,               WkT, 1536);

    // PRE: P[l] = el @ W2 + xl @ W4   (M = L*N, K = 1024, Nout = 512)
    {
        GemmArgs a = {};
        a.A[0] = edge; a.A[1] = node;
        a.Bt = WpT; a.ldB = 1024;
        a.out0 = P;
        run_gemm<MODE_PRE>(a, Lsteps * Nrows, 4, 32);
    }
    // C0 = x0 @ W3 + b_xi
    {
        GemmArgs a = {};
        a.A[0] = x0;
        a.Bt = W3T; a.ldB = 512;
        a.bias0 = b_xi; a.out0 = C0;
        run_gemm<MODE_C0>(a, Nrows, 4, 16);
    }

    for (int l = 0; l < Lsteps; ++l) {
        // xi gate -> X0H, XTH
        {
            GemmArgs a = {};
            a.A[0] = hx;
            a.Bt = W1T; a.ldB = 512;
            a.P = P + (size_t)l * NH; a.C0 = C0; a.x0 = x0;
            a.xl = node + (size_t)l * NH;
            a.out0 = X0H; a.out1 = XTH;
            run_gemm<MODE_XI>(a, Nrows, 4, 16);
        }
        // fused u | r -> U, RH
        {
            GemmArgs a = {};
            a.A[0] = hx; a.A[1] = X0H; a.A[2] = XTH;
            a.Bt = WurT; a.ldB = 1536;
            a.bias0 = b_u; a.bias1 = b_r; a.hx = hx;
            a.out0 = U; a.out1 = RH;
            run_gemm<MODE_UR>(a, Nrows, 8, 48);
        }
        // k + state update -> hx
        {
            GemmArgs a = {};
            a.A[0] = X0H; a.A[1] = XTH; a.A[2] = RH;
            a.Bt = WkT; a.ldB = 1536;
            a.bias0 = b_k; a.U = U; a.hx = hx;
            a.out0 = hx;
            run_gemm<MODE_K>(a, Nrows, 4, 48);
        }
    }
}

// round 4
// speedup vs baseline: 1.1526x; 1.0887x over previous
#include <cuda_runtime.h>
#include <math.h>
#include <stdint.h>

// Problem constants
#define Hdim 512
#define Lsteps 16
#define Nrows 8192
#define NH (Nrows * Hdim)

// ---------------- scratch (device globals) ------------------------------------
__device__ float g_P[Lsteps * (size_t)NH];   // precomputed el@W2 + xl@W4
__device__ float g_C0[NH];                   // x0@W3 + b_xi
__device__ float g_X0H[NH];                  // (1-xi)*x0   (rna-rounded)
__device__ float g_XTH[NH];                  // xi*xl       (rna-rounded)
__device__ float g_RH[NH];                   // r*hx        (rna-rounded)
__device__ float g_U[NH];                    // u gate
// transposed (and tf32-rna-rounded) weights [n][k]
__device__ float g_W1T[512 * 512];
__device__ float g_WpT[512 * 1024];
__device__ float g_W3T[512 * 512];
__device__ float g_WurT[1024 * 1536];
__device__ float g_WkT[512 * 1536];

// ---------------- helpers -------------------------------------------------------
__device__ __forceinline__ uint32_t smem_u32(const void* p) {
    uint32_t a;
    asm("{ .reg .u64 t; cvta.to.shared.u64 t, %1; cvt.u32.u64 %0, t; }" : "=r"(a) : "l"(p));
    return a;
}
__device__ __forceinline__ void cp_async16(float* dst, const float* src) {
    asm volatile("cp.async.cg.shared.global [%0], [%1], 16;"
                 :: "r"(smem_u32(dst)), "l"(src) : "memory");
}
#define CP_COMMIT() asm volatile("cp.async.commit_group;" ::: "memory")
#define CP_WAIT1()  asm volatile("cp.async.wait_group 1;" ::: "memory")

__device__ __forceinline__ float tf32_rna(float x) {
    uint32_t u;
    asm("cvt.rna.tf32.f32 %0, %1;" : "=r"(u) : "f"(x));
    return __uint_as_float(u);
}
__device__ __forceinline__ float sigmoidf_(float x) { return 1.0f / (1.0f + expf(-x)); }

// ---------------- GEMM config ---------------------------------------------------
// CTA 128x128x32, 8 warps (warp tile 64x32), 3-stage cp.async pipeline.
#define BK 32
#define ROW_F 36                       // 32 + 4 pad floats per smem row
#define STAGE_A_F (128 * ROW_F)        // 4608 floats
#define STAGE_F (2 * STAGE_A_F)        // A then B, 9216 floats = 36864 B
#define NSTAGE 3
#define SMEM_BYTES (NSTAGE * STAGE_F * 4)  // 110592

struct GemmArgs {
    const float* A[3];          // K blocks of 512 (row-major, ld = 512)
    const float* Bt;            // transposed weights [Ntot][Ktot]
    int ldB;
    const float* P;
    const float* C0;
    const float* x0;
    const float* xl;
    const float* bias0;
    const float* bias1;
    const float* hx;
    const float* U;
    float* out0;
    float* out1;
};

#define MODE_PRE 0
#define MODE_C0  1
#define MODE_XI  2
#define MODE_UR  3
#define MODE_K   4

template <int MODE>
__device__ __forceinline__ void epi(const GemmArgs& g, int row, int col, float v0, float v1) {
    int c512 = col & 511;
    size_t idx = (size_t)row * Hdim + c512;
    if (MODE == MODE_PRE) {
        *(float2*)(g.out0 + idx) = make_float2(v0, v1);
    } else if (MODE == MODE_C0) {
        float2 b = *(const float2*)(g.bias0 + c512);
        *(float2*)(g.out0 + idx) = make_float2(v0 + b.x, v1 + b.y);
    } else if (MODE == MODE_XI) {
        float2 p   = *(const float2*)(g.P  + idx);
        float2 c0v = *(const float2*)(g.C0 + idx);
        float2 x0v = *(const float2*)(g.x0 + idx);
        float2 xlv = *(const float2*)(g.xl + idx);
        float s0 = sigmoidf_(v0 + p.x + c0v.x);
        float s1 = sigmoidf_(v1 + p.y + c0v.y);
        *(float2*)(g.out0 + idx) = make_float2(tf32_rna((1.f - s0) * x0v.x),
                                               tf32_rna((1.f - s1) * x0v.y));
        *(float2*)(g.out1 + idx) = make_float2(tf32_rna(s0 * xlv.x), tf32_rna(s1 * xlv.y));
    } else if (MODE == MODE_UR) {
        if (col < Hdim) {
            float2 b = *(const float2*)(g.bias0 + c512);
            *(float2*)(g.out0 + idx) = make_float2(sigmoidf_(v0 + b.x), sigmoidf_(v1 + b.y));
        } else {
            float2 b = *(const float2*)(g.bias1 + c512);
            float2 h = *(const float2*)(g.hx + idx);
            *(float2*)(g.out1 + idx) = make_float2(tf32_rna(sigmoidf_(v0 + b.x) * h.x),
                                                   tf32_rna(sigmoidf_(v1 + b.y) * h.y));
        }
    } else { // MODE_K
        float2 b = *(const float2*)(g.bias0 + c512);
        float2 u = *(const float2*)(g.U + idx);
        float2 h = *(const float2*)(g.hx + idx);
        float k0 = tanhf(v0 + b.x), k1 = tanhf(v1 + b.y);
        *(float2*)(g.out0 + idx) = make_float2(tf32_rna((1.f - u.x) * k0 + u.x * h.x),
                                               tf32_rna((1.f - u.y) * k1 + u.y * h.y));
    }
}

// 256 threads: each copies 4 A-chunks + 4 B-chunks of 16B per stage
__device__ __forceinline__ void issue_stage(const GemmArgs& g, int kb, int tid,
                                            int rowBase, int colBase, float* sm) {
    float* As = sm;
    float* Bs = sm + STAGE_A_F;
    int c = tid & 7;                 // 16B chunk within row
    int r = tid >> 3;                // 0..31
    const float* asrc = g.A[kb >> 4] + (size_t)(rowBase + r) * Hdim + (kb & 15) * 32 + c * 4;
    const float* bsrc = g.Bt + (size_t)(colBase + r) * g.ldB + kb * 32 + c * 4;
#pragma unroll
    for (int rr = 0; rr < 4; ++rr) {
        cp_async16(&As[(r + 32 * rr) * ROW_F + c * 4], asrc + (size_t)(32 * rr) * Hdim);
        cp_async16(&Bs[(r + 32 * rr) * ROW_F + c * 4], bsrc + (size_t)(32 * rr) * g.ldB);
    }
}

__device__ __forceinline__ void mma_tf32(float (&d)[4], const uint32_t (&a)[4],
                                         const uint32_t (&b)[2]) {
    asm volatile(
        "mma.sync.aligned.m16n8k8.row.col.f32.tf32.tf32.f32 "
        "{%0,%1,%2,%3}, {%4,%5,%6,%7}, {%8,%9}, {%0,%1,%2,%3};"
        : "+f"(d[0]), "+f"(d[1]), "+f"(d[2]), "+f"(d[3])
        : "r"(a[0]), "r"(a[1]), "r"(a[2]), "r"(a[3]), "r"(b[0]), "r"(b[1]));
}

// warp tile 64(M) x 32(N): 4 i-frags x 4 j-frags
__device__ __forceinline__ void compute_stage(const float* sm, int MW, int NW,
                                              int g, int c, float (&acc)[4][4][4]) {
    const float* As = sm;
    const float* Bs = sm + STAGE_A_F;
#pragma unroll
    for (int kk = 0; kk < BK; kk += 8) {
        uint32_t af[4][4];
        uint32_t bf[4][2];
#pragma unroll
        for (int i = 0; i < 4; ++i) {
            const float* a0 = As + (MW + i * 16 + g) * ROW_F + kk + c;
            af[i][0] = __float_as_uint(a0[0]);
            af[i][1] = __float_as_uint(a0[8 * ROW_F]);
            af[i][2] = __float_as_uint(a0[4]);
            af[i][3] = __float_as_uint(a0[8 * ROW_F + 4]);
        }
#pragma unroll
        for (int j = 0; j < 4; ++j) {
            const float* b0 = Bs + (NW + j * 8 + g) * ROW_F + kk + c;
            bf[j][0] = __float_as_uint(b0[0]);
            bf[j][1] = __float_as_uint(b0[4]);
        }
#pragma unroll
        for (int i = 0; i < 4; ++i)
#pragma unroll
            for (int j = 0; j < 4; ++j)
                mma_tf32(acc[i][j], af[i], bf[j]);
    }
}

template <int MODE>
__global__ void __launch_bounds__(256, 2) gemm_cp(GemmArgs args, int kblocks) {
    extern __shared__ float sm[];
    int tid = threadIdx.x;
    int warp = tid >> 5, lane = tid & 31;
    int MW = (warp & 1) * 64, NW = (warp >> 1) * 32;
    int g = lane >> 2, c = lane & 3;
    int rowBase = blockIdx.x * 128, colBase = blockIdx.y * 128;

    float acc[4][4][4];
#pragma unroll
    for (int i = 0; i < 4; ++i)
#pragma unroll
        for (int j = 0; j < 4; ++j)
#pragma unroll
            for (int e = 0; e < 4; ++e) acc[i][j][e] = 0.0f;

    issue_stage(args, 0, tid, rowBase, colBase, sm);
    CP_COMMIT();
    if (kblocks > 1) issue_stage(args, 1, tid, rowBase, colBase, sm + STAGE_F);
    CP_COMMIT();

    int stage = 0;
    for (int kb = 0; kb < kblocks; ++kb) {
        CP_WAIT1();
        __syncthreads();
        if (kb + 2 < kblocks) {
            int ns = stage + 2;
            if (ns >= NSTAGE) ns -= NSTAGE;
            issue_stage(args, kb + 2, tid, rowBase, colBase, sm + ns * STAGE_F);
        }
        CP_COMMIT();
        compute_stage(sm + stage * STAGE_F, MW, NW, g, c, acc);
        if (++stage == NSTAGE) stage = 0;
    }

    // epilogue
#pragma unroll
    for (int i = 0; i < 4; ++i) {
#pragma unroll
        for (int j = 0; j < 4; ++j) {
            int row = rowBase + MW + i * 16 + g;
            int col = colBase + NW + j * 8 + 2 * c;
            epi<MODE>(args, row, col, acc[i][j][0], acc[i][j][1]);
            epi<MODE>(args, row + 8, col, acc[i][j][2], acc[i][j][3]);
        }
    }
}

// ---------------- fused weight transpose (+ tf32 rna) ---------------------------
// One launch for all 7 transpose jobs. dst[n][k] = rna(src[k][n]).
struct TransJobs {
    const float* src[7];
    float* dst[7];
    int dstld[7];
    int ktiles[7];     // K/32
    int tileofs[7];    // cumulative tile offset
};

__global__ void transposeAll(TransJobs J) {
    __shared__ float t[32][33];
    int bid = blockIdx.x;
    int job = 0;
#pragma unroll
    for (int i = 1; i < 7; ++i)
        if (bid >= J.tileofs[i]) job = i;
    int local = bid - J.tileofs[job];
    int kt = J.ktiles[job];
    int kb = (local % kt) * 32;
    int nb = (local / kt) * 32;
    const float* src = J.src[job];
    float* dst = J.dst[job];
    int dstld = J.dstld[job];
    int tx = threadIdx.x, ty = threadIdx.y;
#pragma unroll
    for (int i = 0; i < 32; i += 8)
        t[ty + i][tx] = src[(size_t)(kb + ty + i) * 512 + nb + tx];
    __syncthreads();
#pragma unroll
    for (int i = 0; i < 32; i += 8)
        dst[(size_t)(nb + ty + i) * dstld + kb + tx] = tf32_rna(t[tx][ty + i]);
}

// ---------------- host -----------------------------------------------------------
template <int MODE>
static void run_gemm(const GemmArgs& a, int M, int nTiles, int kblocks) {
    cudaFuncSetAttribute(gemm_cp<MODE>, cudaFuncAttributeMaxDynamicSharedMemorySize,
                         SMEM_BYTES);
    dim3 grid(M / 128, nTiles);
    gemm_cp<MODE><<<grid, 256, SMEM_BYTES>>>(a, kblocks);
}

extern "C" void kernel_launch(void* const* d_in, const int* in_sizes, int n_in,
                              void* d_out, int out_size) {
    const float* edge = (const float*)d_in[0];
    const float* node = (const float*)d_in[1];
    const float* W_xi = (const float*)d_in[2];
    const float* b_xi = (const float*)d_in[3];
    const float* W_u  = (const float*)d_in[4];
    const float* b_u  = (const float*)d_in[5];
    const float* W_r  = (const float*)d_in[6];
    const float* b_r  = (const float*)d_in[7];
    const float* W_k  = (const float*)d_in[8];
    const float* b_k  = (const float*)d_in[9];
    float* hx = (float*)d_out;

    float *P, *C0, *X0H, *XTH, *RH, *U, *W1T, *WpT, *W3T, *WurT, *WkT;
    cudaGetSymbolAddress((void**)&P,    g_P);
    cudaGetSymbolAddress((void**)&C0,   g_C0);
    cudaGetSymbolAddress((void**)&X0H,  g_X0H);
    cudaGetSymbolAddress((void**)&XTH,  g_XTH);
    cudaGetSymbolAddress((void**)&RH,   g_RH);
    cudaGetSymbolAddress((void**)&U,    g_U);
    cudaGetSymbolAddress((void**)&W1T,  g_W1T);
    cudaGetSymbolAddress((void**)&WpT,  g_WpT);
    cudaGetSymbolAddress((void**)&W3T,  g_W3T);
    cudaGetSymbolAddress((void**)&WurT, g_WurT);
    cudaGetSymbolAddress((void**)&WkT,  g_WkT);

    const float* x0 = node + (size_t)Lsteps * NH;

    cudaMemsetAsync(d_out, 0, (size_t)out_size * sizeof(float), 0);

    // fused transpose of all weight blocks into K-major [n][k] with tf32 rounding
    {
        TransJobs J;
        const float* srcs[7] = {W_xi, W_xi + 512 * 512, W_xi + 1536 * 512,
                                W_xi + 1024 * 512, W_u, W_r, W_k};
        float* dsts[7] = {W1T, WpT, WpT + 512, W3T, WurT,
                          WurT + (size_t)512 * 1536, WkT};
        int lds[7] = {512, 1024, 1024, 512, 1536, 1536, 1536};
        int kts[7] = {16, 16, 16, 16, 48, 48, 48};
        int ofs = 0;
        for (int i = 0; i < 7; ++i) {
            J.src[i] = srcs[i]; J.dst[i] = dsts[i]; J.dstld[i] = lds[i];
            J.ktiles[i] = kts[i]; J.tileofs[i] = ofs;
            ofs += kts[i] * 16;
        }
        transposeAll<<<ofs, dim3(32, 8)>>>(J);
    }

    // PRE: P[l] = el @ W2 + xl @ W4   (M = L*N, K = 1024, Nout = 512)
    {
        GemmArgs a = {};
        a.A[0] = edge; a.A[1] = node;
        a.Bt = WpT; a.ldB = 1024;
        a.out0 = P;
        run_gemm<MODE_PRE>(a, Lsteps * Nrows, 4, 32);
    }
    // C0 = x0 @ W3 + b_xi
    {
        GemmArgs a = {};
        a.A[0] = x0;
        a.Bt = W3T; a.ldB = 512;
        a.bias0 = b_xi; a.out0 = C0;
        run_gemm<MODE_C0>(a, Nrows, 4, 16);
    }

    for (int l = 0; l < Lsteps; ++l) {
        // xi gate -> X0H, XTH
        {
            GemmArgs a = {};
            a.A[0] = hx;
            a.Bt = W1T; a.ldB = 512;
            a.P = P + (size_t)l * NH; a.C0 = C0; a.x0 = x0;
            a.xl = node + (size_t)l * NH;
            a.out0 = X0H; a.out1 = XTH;
            run_gemm<MODE_XI>(a, Nrows, 4, 16);
        }
        // fused u | r -> U, RH
        {
            GemmArgs a = {};
            a.A[0] = hx; a.A[1] = X0H; a.A[2] = XTH;
            a.Bt = WurT; a.ldB = 1536;
            a.bias0 = b_u; a.bias1 = b_r; a.hx = hx;
            a.out0 = U; a.out1 = RH;
            run_gemm<MODE_UR>(a, Nrows, 8, 48);
        }
        // k + state update -> hx
        {
            GemmArgs a = {};
            a.A[0] = X0H; a.A[1] = XTH; a.A[2] = RH;
            a.Bt = WkT; a.ldB = 1536;
            a.bias0 = b_k; a.U = U; a.hx = hx;
            a.out0 = hx;
            run_gemm<MODE_K>(a, Nrows, 4, 48);
        }
    }
}

// round 5
// speedup vs baseline: 1.9466x; 1.6888x over previous
#include <cuda_runtime.h>
#include <cuda_fp16.h>
#include <math.h>
#include <stdint.h>

// Problem constants
#define Hdim 512
#define Lsteps 16
#define Nrows 8192
#define NH (Nrows * Hdim)

// ---------------- scratch (device globals) ------------------------------------
__device__ float g_P[Lsteps * (size_t)NH];   // precomputed el@W2 + xl@W4 (fp32)
__device__ float g_C0[NH];                   // x0@W3 + b_xi (fp32)
__device__ float g_U[NH];                    // u gate (fp32)
// fp16 activations / inputs
__device__ __half g_E16[Lsteps * (size_t)NH];
__device__ __half g_N16[(Lsteps + 1) * (size_t)NH];
__device__ __half g_X0H16[NH];
__device__ __half g_XTH16[NH];
__device__ __half g_RH16[NH];
__device__ __half g_HX16[NH];
// fp16 transposed weights [n][k]
__device__ __half g_W1T[512 * 512];
__device__ __half g_WpT[512 * 1024];
__device__ __half g_W3T[512 * 512];
__device__ __half g_WurT[1024 * 1536];
__device__ __half g_WkT[512 * 1536];

// ---------------- helpers -------------------------------------------------------
__device__ __forceinline__ uint32_t smem_u32(const void* p) {
    uint32_t a;
    asm("{ .reg .u64 t; cvta.to.shared.u64 t, %1; cvt.u32.u64 %0, t; }" : "=r"(a) : "l"(p));
    return a;
}
__device__ __forceinline__ void cp_async16(void* dst, const void* src) {
    asm volatile("cp.async.cg.shared.global [%0], [%1], 16;"
                 :: "r"(smem_u32(dst)), "l"(src) : "memory");
}
#define CP_COMMIT() asm volatile("cp.async.commit_group;" ::: "memory")
#define CP_WAIT1()  asm volatile("cp.async.wait_group 1;" ::: "memory")

__device__ __forceinline__ void ldsm_x4(uint32_t (&r)[4], uint32_t addr) {
    asm volatile("ldmatrix.sync.aligned.m8n8.x4.shared.b16 {%0,%1,%2,%3}, [%4];"
                 : "=r"(r[0]), "=r"(r[1]), "=r"(r[2]), "=r"(r[3]) : "r"(addr));
}
__device__ __forceinline__ void mma_f16(float (&d)[4], const uint32_t (&a)[4],
                                        uint32_t b0, uint32_t b1) {
    asm volatile(
        "mma.sync.aligned.m16n8k16.row.col.f32.f16.f16.f32 "
        "{%0,%1,%2,%3}, {%4,%5,%6,%7}, {%8,%9}, {%0,%1,%2,%3};"
        : "+f"(d[0]), "+f"(d[1]), "+f"(d[2]), "+f"(d[3])
        : "r"(a[0]), "r"(a[1]), "r"(a[2]), "r"(a[3]), "r"(b0), "r"(b1));
}
__device__ __forceinline__ float sigmoidf_(float x) { return 1.0f / (1.0f + expf(-x)); }

// ---------------- GEMM config ---------------------------------------------------
// CTA 128x128x64 fp16, 8 warps (warp tile 64x32), 3-stage cp.async pipeline.
#define AROW_B 144                      // 64 fp16 (128B) + 16B pad
#define STAGE_A_B (128 * AROW_B)        // 18432 B
#define STAGE_B (2 * STAGE_A_B)         // 36864 B (A rows then B rows)
#define NSTAGE 3
#define SMEM_BYTES (NSTAGE * STAGE_B)   // 110592

struct GemmArgs {
    const __half* A[3];         // K blocks of 512 (row-major fp16, ld = 512)
    const __half* Bt;           // transposed fp16 weights [Ntot][Ktot]
    int ldB;
    const float* P;
    const float* C0;
    const float* x0;
    const float* xl;
    const float* bias0;
    const float* bias1;
    const float* hx;
    const float* U;
    float* out0;
    __half* out16a;
    __half* out16b;
};

#define MODE_PRE 0
#define MODE_C0  1
#define MODE_XI  2
#define MODE_UR  3
#define MODE_K   4

template <int MODE>
__device__ __forceinline__ void epi(const GemmArgs& g, int row, int col, float v0, float v1) {
    int c512 = col & 511;
    size_t idx = (size_t)row * Hdim + c512;
    if (MODE == MODE_PRE) {
        *(float2*)(g.out0 + idx) = make_float2(v0, v1);
    } else if (MODE == MODE_C0) {
        float2 b = *(const float2*)(g.bias0 + c512);
        *(float2*)(g.out0 + idx) = make_float2(v0 + b.x, v1 + b.y);
    } else if (MODE == MODE_XI) {
        float2 p   = *(const float2*)(g.P  + idx);
        float2 c0v = *(const float2*)(g.C0 + idx);
        float2 x0v = *(const float2*)(g.x0 + idx);
        float2 xlv = *(const float2*)(g.xl + idx);
        float s0 = sigmoidf_(v0 + p.x + c0v.x);
        float s1 = sigmoidf_(v1 + p.y + c0v.y);
        *(__half2*)(g.out16a + idx) = __floats2half2_rn((1.f - s0) * x0v.x, (1.f - s1) * x0v.y);
        *(__half2*)(g.out16b + idx) = __floats2half2_rn(s0 * xlv.x, s1 * xlv.y);
    } else if (MODE == MODE_UR) {
        if (col < Hdim) {
            float2 b = *(const float2*)(g.bias0 + c512);
            *(float2*)(g.out0 + idx) = make_float2(sigmoidf_(v0 + b.x), sigmoidf_(v1 + b.y));
        } else {
            float2 b = *(const float2*)(g.bias1 + c512);
            float2 h = *(const float2*)(g.hx + idx);
            *(__half2*)(g.out16b + idx) = __floats2half2_rn(sigmoidf_(v0 + b.x) * h.x,
                                                            sigmoidf_(v1 + b.y) * h.y);
        }
    } else { // MODE_K
        float2 b = *(const float2*)(g.bias0 + c512);
        float2 u = *(const float2*)(g.U + idx);
        float2 h = *(const float2*)(g.hx + idx);
        float k0 = tanhf(v0 + b.x), k1 = tanhf(v1 + b.y);
        float r0 = (1.f - u.x) * k0 + u.x * h.x;
        float r1 = (1.f - u.y) * k1 + u.y * h.y;
        *(float2*)(g.out0 + idx) = make_float2(r0, r1);
        *(__half2*)(g.out16a + idx) = __floats2half2_rn(r0, r1);
    }
}

// 256 threads: each copies 4 A-chunks + 4 B-chunks of 16B (8 fp16) per stage
__device__ __forceinline__ void issue_stage(const GemmArgs& g, int kb, int tid,
                                            int rowBase, int colBase, char* sm) {
    int c = tid & 7;                 // 16B chunk within 128B row
    int r = tid >> 3;                // 0..31
    const __half* asrc = g.A[kb >> 3] + (size_t)(rowBase + r) * 512 + (kb & 7) * 64 + c * 8;
    const __half* bsrc = g.Bt + (size_t)(colBase + r) * g.ldB + kb * 64 + c * 8;
    char* As = sm;
    char* Bs = sm + STAGE_A_B;
#pragma unroll
    for (int rr = 0; rr < 4; ++rr) {
        cp_async16(As + (r + 32 * rr) * AROW_B + c * 16, asrc + (size_t)(32 * rr) * 512);
        cp_async16(Bs + (r + 32 * rr) * AROW_B + c * 16, bsrc + (size_t)(32 * rr) * g.ldB);
    }
}

// warp tile 64(M) x 32(N), BK=64: 4 k16-steps; 6 ldmatrix.x4 + 16 mma per step
__device__ __forceinline__ void compute_stage(uint32_t base, uint32_t a_off, uint32_t b_off,
                                              float (&acc)[4][4][4]) {
#pragma unroll
    for (int kk = 0; kk < 4; ++kk) {
        uint32_t a[4][4];
        uint32_t b[2][4];
#pragma unroll
        for (int i = 0; i < 4; ++i)
            ldsm_x4(a[i], base + a_off + kk * 32 + i * (16 * AROW_B));
#pragma unroll
        for (int jj = 0; jj < 2; ++jj)
            ldsm_x4(b[jj], base + b_off + kk * 32 + jj * (16 * AROW_B));
#pragma unroll
        for (int i = 0; i < 4; ++i)
#pragma unroll
            for (int j = 0; j < 4; ++j)
                mma_f16(acc[i][j], a[i], b[j >> 1][(j & 1) * 2], b[j >> 1][(j & 1) * 2 + 1]);
    }
}

template <int MODE>
__global__ void __launch_bounds__(256, 2) gemm_cp(GemmArgs args, int kblocks) {
    extern __shared__ char sm[];
    uint32_t su = smem_u32(sm);
    int tid = threadIdx.x;
    int warp = tid >> 5, lane = tid & 31;
    int MW = (warp & 1) * 64, NW = (warp >> 1) * 32;
    int g = lane >> 2, c = lane & 3;
    int rowBase = blockIdx.x * 128, colBase = blockIdx.y * 128;

    // ldmatrix lane address offsets (bytes within stage)
    uint32_t a_off = (uint32_t)((MW + (lane & 15)) * AROW_B + (lane >> 4) * 16);
    uint32_t b_off = (uint32_t)(STAGE_A_B + (NW + (lane & 7) + ((lane >> 4) << 3)) * AROW_B
                                + ((lane >> 3) & 1) * 16);

    float acc[4][4][4];
#pragma unroll
    for (int i = 0; i < 4; ++i)
#pragma unroll
        for (int j = 0; j < 4; ++j)
#pragma unroll
            for (int e = 0; e < 4; ++e) acc[i][j][e] = 0.0f;

    issue_stage(args, 0, tid, rowBase, colBase, sm);
    CP_COMMIT();
    if (kblocks > 1) issue_stage(args, 1, tid, rowBase, colBase, sm + STAGE_B);
    CP_COMMIT();

    int stage = 0;
    for (int kb = 0; kb < kblocks; ++kb) {
        CP_WAIT1();
        __syncthreads();
        if (kb + 2 < kblocks) {
            int ns = stage + 2;
            if (ns >= NSTAGE) ns -= NSTAGE;
            issue_stage(args, kb + 2, tid, rowBase, colBase, sm + ns * STAGE_B);
        }
        CP_COMMIT();
        compute_stage(su + stage * STAGE_B, a_off, b_off, acc);
        if (++stage == NSTAGE) stage = 0;
    }

    // epilogue
#pragma unroll
    for (int i = 0; i < 4; ++i) {
#pragma unroll
        for (int j = 0; j < 4; ++j) {
            int row = rowBase + MW + i * 16 + g;
            int col = colBase + NW + j * 8 + 2 * c;
            epi<MODE>(args, row, col, acc[i][j][0], acc[i][j][1]);
            epi<MODE>(args, row + 8, col, acc[i][j][2], acc[i][j][3]);
        }
    }
}

// ---------------- fused weight transpose (fp32 -> fp16 [n][k]) ------------------
struct TransJobs {
    const float* src[7];
    __half* dst[7];
    int dstld[7];
    int ktiles[7];
    int tileofs[7];
};

__global__ void transposeAll(TransJobs J) {
    __shared__ float t[32][33];
    int bid = blockIdx.x;
    int job = 0;
#pragma unroll
    for (int i = 1; i < 7; ++i)
        if (bid >= J.tileofs[i]) job = i;
    int local = bid - J.tileofs[job];
    int kt = J.ktiles[job];
    int kb = (local % kt) * 32;
    int nb = (local / kt) * 32;
    const float* src = J.src[job];
    __half* dst = J.dst[job];
    int dstld = J.dstld[job];
    int tx = threadIdx.x, ty = threadIdx.y;
#pragma unroll
    for (int i = 0; i < 32; i += 8)
        t[ty + i][tx] = src[(size_t)(kb + ty + i) * 512 + nb + tx];
    __syncthreads();
#pragma unroll
    for (int i = 0; i < 32; i += 8)
        dst[(size_t)(nb + ty + i) * dstld + kb + tx] = __float2half_rn(t[tx][ty + i]);
}

// ---------------- fp32 -> fp16 bulk convert -------------------------------------
__global__ void f2h8(const float* __restrict__ src, __half* __restrict__ dst, int n) {
    int i = (blockIdx.x * blockDim.x + threadIdx.x) * 8;
    if (i >= n) return;
    float4 v0 = *(const float4*)(src + i);
    float4 v1 = *(const float4*)(src + i + 4);
    __half2 h[4] = {__floats2half2_rn(v0.x, v0.y), __floats2half2_rn(v0.z, v0.w),
                    __floats2half2_rn(v1.x, v1.y), __floats2half2_rn(v1.z, v1.w)};
    *(uint4*)(dst + i) = *(uint4*)h;
}

// ---------------- host -----------------------------------------------------------
template <int MODE>
static void run_gemm(const GemmArgs& a, int M, int nTiles, int kblocks) {
    cudaFuncSetAttribute(gemm_cp<MODE>, cudaFuncAttributeMaxDynamicSharedMemorySize,
                         SMEM_BYTES);
    dim3 grid(M / 128, nTiles);
    gemm_cp<MODE><<<grid, 256, SMEM_BYTES>>>(a, kblocks);
}

extern "C" void kernel_launch(void* const* d_in, const int* in_sizes, int n_in,
                              void* d_out, int out_size) {
    const float* edge = (const float*)d_in[0];
    const float* node = (const float*)d_in[1];
    const float* W_xi = (const float*)d_in[2];
    const float* b_xi = (const float*)d_in[3];
    const float* W_u  = (const float*)d_in[4];
    const float* b_u  = (const float*)d_in[5];
    const float* W_r  = (const float*)d_in[6];
    const float* b_r  = (const float*)d_in[7];
    const float* W_k  = (const float*)d_in[8];
    const float* b_k  = (const float*)d_in[9];
    float* hx = (float*)d_out;

    float *P, *C0, *U;
    __half *E16, *N16, *X0H16, *XTH16, *RH16, *HX16, *W1T, *WpT, *W3T, *WurT, *WkT;
    cudaGetSymbolAddress((void**)&P,     g_P);
    cudaGetSymbolAddress((void**)&C0,    g_C0);
    cudaGetSymbolAddress((void**)&U,     g_U);
    cudaGetSymbolAddress((void**)&E16,   g_E16);
    cudaGetSymbolAddress((void**)&N16,   g_N16);
    cudaGetSymbolAddress((void**)&X0H16, g_X0H16);
    cudaGetSymbolAddress((void**)&XTH16, g_XTH16);
    cudaGetSymbolAddress((void**)&RH16,  g_RH16);
    cudaGetSymbolAddress((void**)&HX16,  g_HX16);
    cudaGetSymbolAddress((void**)&W1T,   g_W1T);
    cudaGetSymbolAddress((void**)&WpT,   g_WpT);
    cudaGetSymbolAddress((void**)&W3T,   g_W3T);
    cudaGetSymbolAddress((void**)&WurT,  g_WurT);
    cudaGetSymbolAddress((void**)&WkT,   g_WkT);

    const float* x0 = node + (size_t)Lsteps * NH;

    cudaMemsetAsync(d_out, 0, (size_t)out_size * sizeof(float), 0);
    cudaMemsetAsync(HX16, 0, (size_t)NH * sizeof(__half), 0);

    // fp32 -> fp16 for edge / node (incl. x0)
    {
        int nE = Lsteps * NH;
        int nN = (Lsteps + 1) * NH;
        f2h8<<<(nE / 8 + 255) / 256, 256>>>(edge, E16, nE);
        f2h8<<<(nN / 8 + 255) / 256, 256>>>(node, N16, nN);
    }

    // fused weight transpose -> fp16 [n][k]
    {
        TransJobs J;
        const float* srcs[7] = {W_xi, W_xi + 512 * 512, W_xi + 1536 * 512,
                                W_xi + 1024 * 512, W_u, W_r, W_k};
        __half* dsts[7] = {W1T, WpT, WpT + 512, W3T, WurT,
                           WurT + (size_t)512 * 1536, WkT};
        int lds[7] = {512, 1024, 1024, 512, 1536, 1536, 1536};
        int kts[7] = {16, 16, 16, 16, 48, 48, 48};
        int ofs = 0;
        for (int i = 0; i < 7; ++i) {
            J.src[i] = srcs[i]; J.dst[i] = dsts[i]; J.dstld[i] = lds[i];
            J.ktiles[i] = kts[i]; J.tileofs[i] = ofs;
            ofs += kts[i] * 16;
        }
        transposeAll<<<ofs, dim3(32, 8)>>>(J);
    }

    // PRE: P[l] = el @ W2 + xl @ W4   (M = L*N, K = 1024, Nout = 512)
    {
        GemmArgs a = {};
        a.A[0] = E16; a.A[1] = N16;
        a.Bt = WpT; a.ldB = 1024;
        a.out0 = P;
        run_gemm<MODE_PRE>(a, Lsteps * Nrows, 4, 16);
    }
    // C0 = x0 @ W3 + b_xi
    {
        GemmArgs a = {};
        a.A[0] = N16 + (size_t)Lsteps * NH;
        a.Bt = W3T; a.ldB = 512;
        a.bias0 = b_xi; a.out0 = C0;
        run_gemm<MODE_C0>(a, Nrows, 4, 8);
    }

    for (int l = 0; l < Lsteps; ++l) {
        // xi gate -> X0H16, XTH16
        {
            GemmArgs a = {};
            a.A[0] = HX16;
            a.Bt = W1T; a.ldB = 512;
            a.P = P + (size_t)l * NH; a.C0 = C0; a.x0 = x0;
            a.xl = node + (size_t)l * NH;
            a.out16a = X0H16; a.out16b = XTH16;
            run_gemm<MODE_XI>(a, Nrows, 4, 8);
        }
        // fused u | r -> U (fp32), RH16
        {
            GemmArgs a = {};
            a.A[0] = HX16; a.A[1] = X0H16; a.A[2] = XTH16;
            a.Bt = WurT; a.ldB = 1536;
            a.bias0 = b_u; a.bias1 = b_r; a.hx = hx;
            a.out0 = U; a.out16b = RH16;
            run_gemm<MODE_UR>(a, Nrows, 8, 24);
        }
        // k + state update -> hx (fp32) + HX16
        {
            GemmArgs a = {};
            a.A[0] = X0H16; a.A[1] = XTH16; a.A[2] = RH16;
            a.Bt = WkT; a.ldB = 1536;
            a.bias0 = b_k; a.U = U; a.hx = hx;
            a.out0 = hx; a.out16a = HX16;
            run_gemm<MODE_K>(a, Nrows, 4, 24);
        }
    }
}

// round 6
// speedup vs baseline: 2.0655x; 1.0611x over previous
#include <cuda_runtime.h>
#include <cuda_fp16.h>
#include <math.h>
#include <stdint.h>

// Problem constants
#define Hdim 512
#define Lsteps 16
#define Nrows 8192
#define NH (Nrows * Hdim)

// ---------------- scratch (device globals) ------------------------------------
__device__ __half g_P[Lsteps * (size_t)NH];  // precomputed el@W2 + xl@W4 (fp16)
__device__ __half g_C0[NH];                  // x0@W3 + b_xi (fp16)
__device__ __half g_U[NH];                   // u gate (fp16)
// fp16 activations / inputs
__device__ __half g_E16[Lsteps * (size_t)NH];
__device__ __half g_N16[(Lsteps + 1) * (size_t)NH];
__device__ __half g_X0H16[NH];
__device__ __half g_XTH16[NH];
__device__ __half g_RH16[NH];
__device__ __half g_HX16[NH];
// fp16 transposed weights [n][k]
__device__ __half g_W1T[512 * 512];
__device__ __half g_WpT[512 * 1024];
__device__ __half g_W3T[512 * 512];
__device__ __half g_WurT[1024 * 1536];
__device__ __half g_WkT[512 * 1536];

// ---------------- helpers -------------------------------------------------------
__device__ __forceinline__ uint32_t smem_u32(const void* p) {
    uint32_t a;
    asm("{ .reg .u64 t; cvta.to.shared.u64 t, %1; cvt.u32.u64 %0, t; }" : "=r"(a) : "l"(p));
    return a;
}
__device__ __forceinline__ void cp_async16(void* dst, const void* src) {
    asm volatile("cp.async.cg.shared.global [%0], [%1], 16;"
                 :: "r"(smem_u32(dst)), "l"(src) : "memory");
}
#define CP_COMMIT() asm volatile("cp.async.commit_group;" ::: "memory")
#define CP_WAIT1()  asm volatile("cp.async.wait_group 1;" ::: "memory")

__device__ __forceinline__ void ldsm_x4(uint32_t (&r)[4], uint32_t addr) {
    asm volatile("ldmatrix.sync.aligned.m8n8.x4.shared.b16 {%0,%1,%2,%3}, [%4];"
                 : "=r"(r[0]), "=r"(r[1]), "=r"(r[2]), "=r"(r[3]) : "r"(addr));
}
__device__ __forceinline__ void mma_f16(float (&d)[4], const uint32_t (&a)[4],
                                        uint32_t b0, uint32_t b1) {
    asm volatile(
        "mma.sync.aligned.m16n8k16.row.col.f32.f16.f16.f32 "
        "{%0,%1,%2,%3}, {%4,%5,%6,%7}, {%8,%9}, {%0,%1,%2,%3};"
        : "+f"(d[0]), "+f"(d[1]), "+f"(d[2]), "+f"(d[3])
        : "r"(a[0]), "r"(a[1]), "r"(a[2]), "r"(a[3]), "r"(b0), "r"(b1));
}
__device__ __forceinline__ float sigmoidf_(float x) { return 1.0f / (1.0f + expf(-x)); }

// ---------------- GEMM config ---------------------------------------------------
// CTA 128x128x64 fp16, 8 warps (warp tile 64x32), 3-stage cp.async pipeline.
#define AROW_B 144                      // 64 fp16 (128B) + 16B pad
#define STAGE_A_B (128 * AROW_B)        // 18432 B
#define STAGE_B (2 * STAGE_A_B)         // 36864 B (A rows then B rows)
#define NSTAGE 3
#define SMEM_BYTES (NSTAGE * STAGE_B)   // 110592

struct GemmArgs {
    const __half* A[3];         // K blocks of 512 (row-major fp16, ld = 512)
    const __half* Bt;           // transposed fp16 weights [Ntot][Ktot]
    int ldB;
    const __half* P;
    const __half* C0;
    const __half* x0;
    const __half* xl;
    const float* bias0;
    const float* bias1;
    const float* hx;
    const __half* U;
    float* out0;
    __half* out16a;
    __half* out16b;
};

#define MODE_PRE 0
#define MODE_C0  1
#define MODE_XI  2
#define MODE_UR  3
#define MODE_K   4

__device__ __forceinline__ float2 h2f(const __half* p) {
    return __half22float2(*(const __half2*)p);
}

template <int MODE>
__device__ __forceinline__ void epi(const GemmArgs& g, int row, int col, float v0, float v1) {
    int c512 = col & 511;
    size_t idx = (size_t)row * Hdim + c512;
    if (MODE == MODE_PRE) {
        *(__half2*)(g.out16a + idx) = __floats2half2_rn(v0, v1);
    } else if (MODE == MODE_C0) {
        float2 b = *(const float2*)(g.bias0 + c512);
        *(__half2*)(g.out16a + idx) = __floats2half2_rn(v0 + b.x, v1 + b.y);
    } else if (MODE == MODE_XI) {
        float2 p   = h2f(g.P  + idx);
        float2 c0v = h2f(g.C0 + idx);
        float2 x0v = h2f(g.x0 + idx);
        float2 xlv = h2f(g.xl + idx);
        float s0 = sigmoidf_(v0 + p.x + c0v.x);
        float s1 = sigmoidf_(v1 + p.y + c0v.y);
        *(__half2*)(g.out16a + idx) = __floats2half2_rn((1.f - s0) * x0v.x, (1.f - s1) * x0v.y);
        *(__half2*)(g.out16b + idx) = __floats2half2_rn(s0 * xlv.x, s1 * xlv.y);
    } else if (MODE == MODE_UR) {
        if (col < Hdim) {
            float2 b = *(const float2*)(g.bias0 + c512);
            *(__half2*)(g.out16a + idx) = __floats2half2_rn(sigmoidf_(v0 + b.x),
                                                            sigmoidf_(v1 + b.y));
        } else {
            float2 b = *(const float2*)(g.bias1 + c512);
            float2 h = *(const float2*)(g.hx + idx);
            *(__half2*)(g.out16b + idx) = __floats2half2_rn(sigmoidf_(v0 + b.x) * h.x,
                                                            sigmoidf_(v1 + b.y) * h.y);
        }
    } else { // MODE_K
        float2 b = *(const float2*)(g.bias0 + c512);
        float2 u = h2f(g.U + idx);
        float2 h = *(const float2*)(g.hx + idx);
        float k0 = tanhf(v0 + b.x), k1 = tanhf(v1 + b.y);
        float r0 = (1.f - u.x) * k0 + u.x * h.x;
        float r1 = (1.f - u.y) * k1 + u.y * h.y;
        *(float2*)(g.out0 + idx) = make_float2(r0, r1);
        *(__half2*)(g.out16a + idx) = __floats2half2_rn(r0, r1);
    }
}

// 256 threads: each copies 4 A-chunks + 4 B-chunks of 16B (8 fp16) per stage
__device__ __forceinline__ void issue_stage(const GemmArgs& g, int kb, int tid,
                                            int rowBase, int colBase, char* sm) {
    int c = tid & 7;                 // 16B chunk within 128B row
    int r = tid >> 3;                // 0..31
    const __half* asrc = g.A[kb >> 3] + (size_t)(rowBase + r) * 512 + (kb & 7) * 64 + c * 8;
    const __half* bsrc = g.Bt + (size_t)(colBase + r) * g.ldB + kb * 64 + c * 8;
    char* As = sm;
    char* Bs = sm + STAGE_A_B;
#pragma unroll
    for (int rr = 0; rr < 4; ++rr) {
        cp_async16(As + (r + 32 * rr) * AROW_B + c * 16, asrc + (size_t)(32 * rr) * 512);
        cp_async16(Bs + (r + 32 * rr) * AROW_B + c * 16, bsrc + (size_t)(32 * rr) * g.ldB);
    }
}

// warp tile 64(M) x 32(N), BK=64: 4 k16-steps; 6 ldmatrix.x4 + 16 mma per step
__device__ __forceinline__ void compute_stage(uint32_t base, uint32_t a_off, uint32_t b_off,
                                              float (&acc)[4][4][4]) {
#pragma unroll
    for (int kk = 0; kk < 4; ++kk) {
        uint32_t a[4][4];
        uint32_t b[2][4];
#pragma unroll
        for (int i = 0; i < 4; ++i)
            ldsm_x4(a[i], base + a_off + kk * 32 + i * (16 * AROW_B));
#pragma unroll
        for (int jj = 0; jj < 2; ++jj)
            ldsm_x4(b[jj], base + b_off + kk * 32 + jj * (16 * AROW_B));
#pragma unroll
        for (int i = 0; i < 4; ++i)
#pragma unroll
            for (int j = 0; j < 4; ++j)
                mma_f16(acc[i][j], a[i], b[j >> 1][(j & 1) * 2], b[j >> 1][(j & 1) * 2 + 1]);
    }
}

template <int MODE>
__global__ void __launch_bounds__(256, 2) gemm_cp(GemmArgs args, int kblocks) {
    extern __shared__ char sm[];
    uint32_t su = smem_u32(sm);
    int tid = threadIdx.x;
    int warp = tid >> 5, lane = tid & 31;
    int MW = (warp & 1) * 64, NW = (warp >> 1) * 32;
    int g = lane >> 2, c = lane & 3;
    // grid-swapped: x = N tile (fast), y = M tile -> N-tiles sharing A co-scheduled
    int rowBase = blockIdx.y * 128, colBase = blockIdx.x * 128;

    // ldmatrix lane address offsets (bytes within stage)
    uint32_t a_off = (uint32_t)((MW + (lane & 15)) * AROW_B + (lane >> 4) * 16);
    uint32_t b_off = (uint32_t)(STAGE_A_B + (NW + (lane & 7) + ((lane >> 4) << 3)) * AROW_B
                                + ((lane >> 3) & 1) * 16);

    float acc[4][4][4];
#pragma unroll
    for (int i = 0; i < 4; ++i)
#pragma unroll
        for (int j = 0; j < 4; ++j)
#pragma unroll
            for (int e = 0; e < 4; ++e) acc[i][j][e] = 0.0f;

    issue_stage(args, 0, tid, rowBase, colBase, sm);
    CP_COMMIT();
    if (kblocks > 1) issue_stage(args, 1, tid, rowBase, colBase, sm + STAGE_B);
    CP_COMMIT();

    int stage = 0;
    for (int kb = 0; kb < kblocks; ++kb) {
        CP_WAIT1();
        __syncthreads();
        if (kb + 2 < kblocks) {
            int ns = stage + 2;
            if (ns >= NSTAGE) ns -= NSTAGE;
            issue_stage(args, kb + 2, tid, rowBase, colBase, sm + ns * STAGE_B);
        }
        CP_COMMIT();
        compute_stage(su + stage * STAGE_B, a_off, b_off, acc);
        if (++stage == NSTAGE) stage = 0;
    }

    // epilogue
#pragma unroll
    for (int i = 0; i < 4; ++i) {
#pragma unroll
        for (int j = 0; j < 4; ++j) {
            int row = rowBase + MW + i * 16 + g;
            int col = colBase + NW + j * 8 + 2 * c;
            epi<MODE>(args, row, col, acc[i][j][0], acc[i][j][1]);
            epi<MODE>(args, row + 8, col, acc[i][j][2], acc[i][j][3]);
        }
    }
}

// ---------------- fused weight transpose (fp32 -> fp16 [n][k]) ------------------
struct TransJobs {
    const float* src[7];
    __half* dst[7];
    int dstld[7];
    int ktiles[7];
    int tileofs[7];
};

__global__ void transposeAll(TransJobs J) {
    __shared__ float t[32][33];
    int bid = blockIdx.x;
    int job = 0;
#pragma unroll
    for (int i = 1; i < 7; ++i)
        if (bid >= J.tileofs[i]) job = i;
    int local = bid - J.tileofs[job];
    int kt = J.ktiles[job];
    int kb = (local % kt) * 32;
    int nb = (local / kt) * 32;
    const float* src = J.src[job];
    __half* dst = J.dst[job];
    int dstld = J.dstld[job];
    int tx = threadIdx.x, ty = threadIdx.y;
#pragma unroll
    for (int i = 0; i < 32; i += 8)
        t[ty + i][tx] = src[(size_t)(kb + ty + i) * 512 + nb + tx];
    __syncthreads();
#pragma unroll
    for (int i = 0; i < 32; i += 8)
        dst[(size_t)(nb + ty + i) * dstld + kb + tx] = __float2half_rn(t[tx][ty + i]);
}

// ---------------- fp32 -> fp16 bulk convert -------------------------------------
__global__ void f2h8(const float* __restrict__ src, __half* __restrict__ dst, int n) {
    int i = (blockIdx.x * blockDim.x + threadIdx.x) * 8;
    if (i >= n) return;
    float4 v0 = *(const float4*)(src + i);
    float4 v1 = *(const float4*)(src + i + 4);
    __half2 h[4] = {__floats2half2_rn(v0.x, v0.y), __floats2half2_rn(v0.z, v0.w),
                    __floats2half2_rn(v1.x, v1.y), __floats2half2_rn(v1.z, v1.w)};
    *(uint4*)(dst + i) = *(uint4*)h;
}

// ---------------- host -----------------------------------------------------------
template <int MODE>
static void run_gemm(const GemmArgs& a, int M, int nTiles, int kblocks) {
    cudaFuncSetAttribute(gemm_cp<MODE>, cudaFuncAttributeMaxDynamicSharedMemorySize,
                         SMEM_BYTES);
    dim3 grid(nTiles, M / 128);      // N tiles fastest -> A reuse within a wave
    gemm_cp<MODE><<<grid, 256, SMEM_BYTES>>>(a, kblocks);
}

extern "C" void kernel_launch(void* const* d_in, const int* in_sizes, int n_in,
                              void* d_out, int out_size) {
    const float* edge = (const float*)d_in[0];
    const float* node = (const float*)d_in[1];
    const float* W_xi = (const float*)d_in[2];
    const float* b_xi = (const float*)d_in[3];
    const float* W_u  = (const float*)d_in[4];
    const float* b_u  = (const float*)d_in[5];
    const float* W_r  = (const float*)d_in[6];
    const float* b_r  = (const float*)d_in[7];
    const float* W_k  = (const float*)d_in[8];
    const float* b_k  = (const float*)d_in[9];
    float* hx = (float*)d_out;

    __half *P, *C0, *U;
    __half *E16, *N16, *X0H16, *XTH16, *RH16, *HX16, *W1T, *WpT, *W3T, *WurT, *WkT;
    cudaGetSymbolAddress((void**)&P,     g_P);
    cudaGetSymbolAddress((void**)&C0,    g_C0);
    cudaGetSymbolAddress((void**)&U,     g_U);
    cudaGetSymbolAddress((void**)&E16,   g_E16);
    cudaGetSymbolAddress((void**)&N16,   g_N16);
    cudaGetSymbolAddress((void**)&X0H16, g_X0H16);
    cudaGetSymbolAddress((void**)&XTH16, g_XTH16);
    cudaGetSymbolAddress((void**)&RH16,  g_RH16);
    cudaGetSymbolAddress((void**)&HX16,  g_HX16);
    cudaGetSymbolAddress((void**)&W1T,   g_W1T);
    cudaGetSymbolAddress((void**)&WpT,   g_WpT);
    cudaGetSymbolAddress((void**)&W3T,   g_W3T);
    cudaGetSymbolAddress((void**)&WurT,  g_WurT);
    cudaGetSymbolAddress((void**)&WkT,   g_WkT);

    cudaMemsetAsync(d_out, 0, (size_t)out_size * sizeof(float), 0);
    cudaMemsetAsync(HX16, 0, (size_t)NH * sizeof(__half), 0);

    // fp32 -> fp16 for edge / node (incl. x0)
    {
        int nE = Lsteps * NH;
        int nN = (Lsteps + 1) * NH;
        f2h8<<<(nE / 8 + 255) / 256, 256>>>(edge, E16, nE);
        f2h8<<<(nN / 8 + 255) / 256, 256>>>(node, N16, nN);
    }

    // fused weight transpose -> fp16 [n][k]
    {
        TransJobs J;
        const float* srcs[7] = {W_xi, W_xi + 512 * 512, W_xi + 1536 * 512,
                                W_xi + 1024 * 512, W_u, W_r, W_k};
        __half* dsts[7] = {W1T, WpT, WpT + 512, W3T, WurT,
                           WurT + (size_t)512 * 1536, WkT};
        int lds[7] = {512, 1024, 1024, 512, 1536, 1536, 1536};
        int kts[7] = {16, 16, 16, 16, 48, 48, 48};
        int ofs = 0;
        for (int i = 0; i < 7; ++i) {
            J.src[i] = srcs[i]; J.dst[i] = dsts[i]; J.dstld[i] = lds[i];
            J.ktiles[i] = kts[i]; J.tileofs[i] = ofs;
            ofs += kts[i] * 16;
        }
        transposeAll<<<ofs, dim3(32, 8)>>>(J);
    }

    const __half* x016 = N16 + (size_t)Lsteps * NH;

    // PRE: P[l] = el @ W2 + xl @ W4   (M = L*N, K = 1024, Nout = 512) -> fp16
    {
        GemmArgs a = {};
        a.A[0] = E16; a.A[1] = N16;
        a.Bt = WpT; a.ldB = 1024;
        a.out16a = P;
        run_gemm<MODE_PRE>(a, Lsteps * Nrows, 4, 16);
    }
    // C0 = x0 @ W3 + b_xi -> fp16
    {
        GemmArgs a = {};
        a.A[0] = x016;
        a.Bt = W3T; a.ldB = 512;
        a.bias0 = b_xi; a.out16a = C0;
        run_gemm<MODE_C0>(a, Nrows, 4, 8);
    }

    for (int l = 0; l < Lsteps; ++l) {
        // xi gate -> X0H16, XTH16
        {
            GemmArgs a = {};
            a.A[0] = HX16;
            a.Bt = W1T; a.ldB = 512;
            a.P = P + (size_t)l * NH; a.C0 = C0;
            a.x0 = x016; a.xl = N16 + (size_t)l * NH;
            a.out16a = X0H16; a.out16b = XTH16;
            run_gemm<MODE_XI>(a, Nrows, 4, 8);
        }
        // fused u | r -> U (fp16), RH16
        {
            GemmArgs a = {};
            a.A[0] = HX16; a.A[1] = X0H16; a.A[2] = XTH16;
            a.Bt = WurT; a.ldB = 1536;
            a.bias0 = b_u; a.bias1 = b_r; a.hx = hx;
            a.out16a = U; a.out16b = RH16;
            run_gemm<MODE_UR>(a, Nrows, 8, 24);
        }
        // k + state update -> hx (fp32) + HX16
        {
            GemmArgs a = {};
            a.A[0] = X0H16; a.A[1] = XTH16; a.A[2] = RH16;
            a.Bt = WkT; a.ldB = 1536;
            a.bias0 = b_k; a.U = U; a.hx = hx;
            a.out0 = hx; a.out16a = HX16;
            run_gemm<MODE_K>(a, Nrows, 4, 24);
        }
    }
}